// round 17
// baseline (speedup 1.0000x reference)
#include <cuda_runtime.h>
#include <cuda_fp16.h>
#include <cstdint>

#define L 2304
#define NBATCH 4
#define CIN 512
#define HCH 64
#define NH 8
#define NNH (NBATCH * NH)        // 32
#define NQT 18                   // q tiles of 128
#define NCHUNK 18                // key chunks of 128
#define NCB 288                  // column blocks of 8 over L

// scratch (no cudaMalloc allowed)
__device__ float g_qkv[NBATCH * 192 * L];        // [n][192][L] fp32
__device__ float g_o[NBATCH * HCH * L];          // [n][64][L]
__device__ __half g_qh[NNH * L * 8];             // [nh][q][8]  (scaled)
__device__ __half g_kh[NNH * L * 8];             // [nh][k][8]
__device__ __half g_vh[NNH * 16 * L];            // [nh][dim16][k], plane8=ones
// fragment images
__device__ uint4 g_qwf[12 * 32 * 32 * 2];        // qkv_w A-frags {hi,lo}
__device__ uint4 g_rwf[32 * 4 * 32 * 2];         // res_w A-frags
__device__ uint4 g_pwf[4 * 36 * 32 * 2];         // pos_w A-frags (64x576)
__device__ uint2 g_xf2[NBATCH * NCB * 32 * 32];  // x B-frags hi-only {bh0,bh1}
__device__ uint2 g_of2[NBATCH * NCB * 4 * 32];   // attn-out B-frags hi-only
__device__ uint2 g_pf2[NBATCH * NCB * 36 * 32];  // pos im2col B-frags hi-only

#define HMMA16(c0, c1, c2, c3, a0, a1, a2, a3, b0, b1) \
    asm volatile("mma.sync.aligned.m16n8k16.row.col.f32.f16.f16.f32 " \
        "{%0,%1,%2,%3}, {%4,%5,%6,%7}, {%8,%9}, {%0,%1,%2,%3};" \
        : "+f"(c0), "+f"(c1), "+f"(c2), "+f"(c3) \
        : "r"(a0), "r"(a1), "r"(a2), "r"(a3), "r"(b0), "r"(b1))

#define HMMA8(c0, c1, c2, c3, a0, a1, b0) \
    asm volatile("mma.sync.aligned.m16n8k8.row.col.f32.f16.f16.f32 " \
        "{%0,%1,%2,%3}, {%4,%5}, {%6}, {%0,%1,%2,%3};" \
        : "+f"(c0), "+f"(c1), "+f"(c2), "+f"(c3) \
        : "r"(a0), "r"(a1), "r"(b0))

__device__ __forceinline__ uint32_t split_pack(float a, float b, uint32_t& lo) {
    __half ha = __float2half_rn(a), hb = __float2half_rn(b);
    __half la = __float2half_rn(a - __half2float(ha));
    __half lb = __float2half_rn(b - __half2float(hb));
    lo = ((uint32_t)__half_as_ushort(lb) << 16) | __half_as_ushort(la);
    return ((uint32_t)__half_as_ushort(hb) << 16) | __half_as_ushort(ha);
}

__device__ __forceinline__ uint32_t pack_h2(float a, float b) {
    __half2 h2 = __floats2half2_rn(a, b);
    return *(uint32_t*)&h2;
}

// ============================================================
// A-fragment builder: src [M][K] fp32 -> {hi,lo} uint4 pairs.
// ============================================================
__global__ void __launch_bounds__(256) afrag_split_kernel(
    const float* __restrict__ src, uint4* __restrict__ dst,
    int K, int NKB, int total)
{
    int id = blockIdx.x * 256 + threadIdx.x;
    if (id >= total) return;
    int lane = id & 31;
    int kblk = (id >> 5) % NKB;
    int mb   = id / (32 * NKB);
    int row = mb * 16 + (lane >> 2);
    int w   = kblk * 8 + (lane & 3);
    const float* s0 = src + (size_t)row * K;
    const float* s1 = s0 + 8 * K;
    uint4 hi, lo;
    hi.x = split_pack(s0[2 * w],     s0[2 * w + 1], lo.x);
    hi.y = split_pack(s1[2 * w],     s1[2 * w + 1], lo.y);
    hi.z = split_pack(s0[2 * w + 8], s0[2 * w + 9], lo.z);
    hi.w = split_pack(s1[2 * w + 8], s1[2 * w + 9], lo.w);
    dst[id * 2]     = hi;
    dst[id * 2 + 1] = lo;
}

// ============================================================
// Smem-staged hi-only B-frag builder.
// CTA = (kblk, 32-cb group, nb): coalesced load of [16 k][256 cols]
// fp32 tile, then emit 1024 uint2 frags with trivial index math.
// ============================================================
template <int NKB>
__global__ void __launch_bounds__(256) bfrag_hi_staged_kernel(
    const float* __restrict__ src, uint2* __restrict__ dst)
{
    __shared__ float s[16][257];
    int kblk = blockIdx.x;
    int cbg  = blockIdx.y;       // 0..8 (32 cb = 256 cols each)
    int nb   = blockIdx.z;
    int t = threadIdx.x;

    const float* sp = src + ((size_t)nb * (NKB * 16) + kblk * 16) * L + cbg * 256;
    {
        int row = t >> 4, c0 = (t & 15) * 16;
        const float* rp = sp + (size_t)row * L + c0;
#pragma unroll
        for (int u = 0; u < 4; u++) {
            float4 v = *(const float4*)(rp + u * 4);
            s[row][c0 + u * 4 + 0] = v.x;
            s[row][c0 + u * 4 + 1] = v.y;
            s[row][c0 + u * 4 + 2] = v.z;
            s[row][c0 + u * 4 + 3] = v.w;
        }
    }
    __syncthreads();

    int cb0 = cbg * 32;
#pragma unroll
    for (int u = 0; u < 4; u++) {
        int e = t + u * 256;
        int cbl = e >> 5, lane = e & 31;
        int col = cbl * 8 + (lane >> 2);
        int wl = (lane & 3) * 2;
        uint2 o;
        o.x = pack_h2(s[wl][col],     s[wl + 1][col]);
        o.y = pack_h2(s[wl + 8][col], s[wl + 9][col]);
        dst[(((size_t)nb * NCB + cb0 + cbl) * NKB + kblk) * 32 + lane] = o;
    }
}

// ============================================================
// Pos-conv im2col B-frag builder (hi-only f16).
// channel k = ic*9+tap, value = V[n][ic][shift(px, tap)].
// ============================================================
__device__ __forceinline__ float pos_im2col(const float* qn, int k, int px) {
    int ic = k / 9;
    int tap = k - ic * 9;
    int dy = tap / 3 - 1, dx = tap - (tap / 3) * 3 - 1;
    int y = px / 48, x = px - y * 48;
    int gy = y + dy, gx = x + dx;
    float v = 0.f;
    if ((unsigned)gy < 48u && (unsigned)gx < 48u) {
        int c = (ic >> 3) * 24 + 16 + (ic & 7);   // V channel in qkv
        v = qn[(size_t)c * L + gy * 48 + gx];
    }
    return v;
}

__global__ void __launch_bounds__(256) pfrag_hi_kernel(int total)
{
    int id = blockIdx.x * 256 + threadIdx.x;
    if (id >= total) return;
    int lane = id & 31;
    int kblk = (id >> 5) % 36;
    int cb   = (id / (32 * 36)) % NCB;
    int nb   = id / (32 * 36 * NCB);
    int px = cb * 8 + (lane >> 2);
    int w  = kblk * 8 + (lane & 3);
    const float* qn = g_qkv + (size_t)nb * 192 * L;
    uint2 o;
    o.x = pack_h2(pos_im2col(qn, 2 * w, px),     pos_im2col(qn, 2 * w + 1, px));
    o.y = pack_h2(pos_im2col(qn, 2 * w + 8, px), pos_im2col(qn, 2 * w + 9, px));
    g_pf2[id] = o;
}

// ============================================================
// Split-A x plain-f16-B HMMA GEMM (2 HMMA/j) — all three GEMMs.
// C[nb][m][l] = sum_k A[m][k]*B[nb][k][l] (+bias).
// ADDMODE=1: atomicAdd into C, bias applied by ky==0.
// grid (36, MBT*KSPLIT, NBATCH), 256 thr = 8 warps (4 m16 x 2 cb4).
// ============================================================
template <int NKB, int KSPLIT, int ADDMODE>
__global__ void __launch_bounds__(256, 3) hgemm_bhi_kernel(
    const uint4* __restrict__ Af, const uint2* __restrict__ Bf,
    const float* __restrict__ bias, float* __restrict__ C,
    int M)
{
    constexpr int kbN = NKB / KSPLIT;
    int t = threadIdx.x, wid = t >> 5, lane = t & 31;
    int mw = wid >> 1, nw = wid & 1;
    int mbt = blockIdx.y / KSPLIT;
    int ky  = blockIdx.y % KSPLIT;
    int mb  = mbt * 4 + mw;
    int cb0 = blockIdx.x * 8 + nw * 4;
    int nb  = blockIdx.z;
    int r = lane >> 2, cq = lane & 3;
    int kb0 = ky * kbN;

    const uint4* pa = Af + ((size_t)mb * NKB + kb0) * 64 + lane * 2;
    const uint2* pb = Bf + (((size_t)nb * NCB + cb0) * NKB + kb0) * 32 + lane;

    float acc[4][4];
#pragma unroll
    for (int j = 0; j < 4; j++)
#pragma unroll
        for (int i = 0; i < 4; i++) acc[j][i] = 0.f;

    uint2 nB[4];
#pragma unroll
    for (int j = 0; j < 4; j++) nB[j] = pb[j * (NKB * 32)];

#pragma unroll 4
    for (int kb = 0; kb < kbN; kb++) {
        uint2 cB[4];
#pragma unroll
        for (int j = 0; j < 4; j++) cB[j] = nB[j];
        uint4 ah = pa[0];
        uint4 al = pa[1];
        if (kb + 1 < kbN) {
            pb += 32;
            pa += 64;
#pragma unroll
            for (int j = 0; j < 4; j++) nB[j] = pb[j * (NKB * 32)];
        }
#pragma unroll
        for (int j = 0; j < 4; j++) {
            HMMA16(acc[j][0], acc[j][1], acc[j][2], acc[j][3],
                   ah.x, ah.y, ah.z, ah.w, cB[j].x, cB[j].y);
            HMMA16(acc[j][0], acc[j][1], acc[j][2], acc[j][3],
                   al.x, al.y, al.z, al.w, cB[j].x, cB[j].y);
        }
    }

    int row0 = mb * 16 + r;
    float b0 = 0.f, b1 = 0.f;
    if (!ADDMODE || ky == 0) { b0 = bias[row0]; b1 = bias[row0 + 8]; }
    float* base0 = C + ((size_t)nb * M + row0) * L;
    float* base1 = base0 + 8 * L;
#pragma unroll
    for (int j = 0; j < 4; j++) {
        int col = (cb0 + j) * 8 + cq * 2;
        float v00 = acc[j][0] + b0;
        float v01 = acc[j][1] + b0;
        float v10 = acc[j][2] + b1;
        float v11 = acc[j][3] + b1;
        if (ADDMODE) {
            atomicAdd(base0 + col,     v00);
            atomicAdd(base0 + col + 1, v01);
            atomicAdd(base1 + col,     v10);
            atomicAdd(base1 + col + 1, v11);
        } else {
            *(float2*)(base0 + col) = make_float2(v00, v01);
            *(float2*)(base1 + col) = make_float2(v10, v11);
        }
    }
}

// ============================================================
// Convert fp32 qkv -> fp16 fragment-friendly images (attention).
// ============================================================
#define NT_Q (NNH * L)
#define NT_K (NNH * L)
#define NT_V (NNH * 16 * (L / 8))

__global__ void __launch_bounds__(256) convert_kernel()
{
    const float QS = 0.35355339059327373f * 1.4426950408889634f;
    int id = blockIdx.x * 256 + threadIdx.x;

    if (id < NT_Q) {
        int nh = id / L, q = id - nh * L;
        int n = nh >> 3, h = nh & 7;
        const float* src = g_qkv + ((size_t)n * 192 + h * 24) * L + q;
        uint32_t w[4];
#pragma unroll
        for (int j = 0; j < 4; j++)
            w[j] = pack_h2(src[(size_t)(2 * j) * L] * QS,
                           src[(size_t)(2 * j + 1) * L] * QS);
        ((uint4*)g_qh)[id] = make_uint4(w[0], w[1], w[2], w[3]);
        return;
    }
    id -= NT_Q;
    if (id < NT_K) {
        int nh = id / L, k = id - nh * L;
        int n = nh >> 3, h = nh & 7;
        const float* src = g_qkv + ((size_t)n * 192 + h * 24 + 8) * L + k;
        uint32_t w[4];
#pragma unroll
        for (int j = 0; j < 4; j++)
            w[j] = pack_h2(src[(size_t)(2 * j) * L], src[(size_t)(2 * j + 1) * L]);
        ((uint4*)g_kh)[id] = make_uint4(w[0], w[1], w[2], w[3]);
        return;
    }
    id -= NT_K;
    if (id < NT_V) {
        int nh = id / (16 * (L / 8));
        int rem = id - nh * 16 * (L / 8);
        int dim = rem / (L / 8);
        int blk = rem - dim * (L / 8);
        uint4 out;
        if (dim < 8) {
            int n = nh >> 3, h = nh & 7;
            const float* src = g_qkv + ((size_t)n * 192 + h * 24 + 16 + dim) * L + blk * 8;
            float4 f0 = *(const float4*)src;
            float4 f1 = *(const float4*)(src + 4);
            out = make_uint4(pack_h2(f0.x, f0.y), pack_h2(f0.z, f0.w),
                             pack_h2(f1.x, f1.y), pack_h2(f1.z, f1.w));
        } else if (dim == 8) {
            out = make_uint4(0x3C003C00u, 0x3C003C00u, 0x3C003C00u, 0x3C003C00u);
        } else {
            out = make_uint4(0, 0, 0, 0);
        }
        ((uint4*)g_vh)[(size_t)(nh * 16 + dim) * (L / 8) + blk] = out;
    }
}

// ============================================================
// Attention via HMMA (f16 in, f32 accum).
// ============================================================
__global__ void __launch_bounds__(256) attn_hmma_kernel()
{
    __shared__ uint32_t sK[2][512];
    __shared__ uint32_t sV[2][16 * 68];
    int t = threadIdx.x, wid = t >> 5, lane = t & 31;
    int bid = blockIdx.x;
    int qt = bid % NQT;
    int nh = bid / NQT;
    int r = lane >> 2, cq = lane & 3;

    const uint32_t* kg = (const uint32_t*)g_kh + (size_t)nh * L * 4;
    const uint32_t* vg = (const uint32_t*)g_vh + (size_t)nh * 16 * (L / 2);

    int q0 = qt * 128 + wid * 16;
    const uint32_t* qgp = (const uint32_t*)g_qh + (size_t)(nh * L + q0) * 4;
    uint32_t qa0 = qgp[r * 4 + cq];
    uint32_t qa1 = qgp[(r + 8) * 4 + cq];
    const uint32_t C15 = 0x4B804B80u;

    int pl = t >> 4, qw = t & 15;

    uint2 kreg = ((const uint2*)kg)[t];
    uint4 vreg = *(const uint4*)(vg + (size_t)pl * (L / 2) + qw * 4);
    ((uint2*)sK[0])[t] = kreg;
    *(uint4*)&sV[0][pl * 68 + qw * 4] = vreg;
    __syncthreads();

    float o0[4] = {0.f, 0.f, 0.f, 0.f};
    float o1[4] = {0.f, 0.f, 0.f, 0.f};

    for (int c = 0; c < NCHUNK; c++) {
        int cur = c & 1;
        if (c + 1 < NCHUNK) {
            kreg = ((const uint2*)(kg + (size_t)(c + 1) * 512))[t];
            vreg = *(const uint4*)(vg + (size_t)pl * (L / 2) + (c + 1) * 64 + qw * 4);
        }

        uint32_t pa[16], pb[16];
#pragma unroll
        for (int j = 0; j < 16; j++) {
            uint32_t kb = sK[cur][j * 32 + r * 4 + cq];
            float s0 = -9.f, s1 = -9.f, s2 = -9.f, s3 = -9.f;
            HMMA8(s0, s1, s2, s3, qa0, qa1, kb);
            uint32_t x, y;
            asm("cvt.rn.f16x2.f32 %0, %1, %2;" : "=r"(x) : "f"(s1), "f"(s0));
            asm("min.f16x2 %0, %0, %1;" : "+r"(x) : "r"(C15));
            asm("ex2.approx.f16x2 %0, %1;" : "=r"(x) : "r"(x));
            asm("cvt.rn.f16x2.f32 %0, %1, %2;" : "=r"(y) : "f"(s3), "f"(s2));
            asm("min.f16x2 %0, %0, %1;" : "+r"(y) : "r"(C15));
            asm("ex2.approx.f16x2 %0, %1;" : "=r"(y) : "r"(y));
            pa[j] = x;
            pb[j] = y;
        }

#pragma unroll
        for (int s = 0; s < 8; s++) {
            uint32_t b0 = sV[cur][r * 68 + s * 8 + cq];
            uint32_t b1 = sV[cur][r * 68 + s * 8 + cq + 4];
            HMMA16(o0[0], o0[1], o0[2], o0[3],
                   pa[2 * s], pb[2 * s], pa[2 * s + 1], pb[2 * s + 1], b0, b1);
            uint32_t b2 = sV[cur][(r + 8) * 68 + s * 8 + cq];
            uint32_t b3 = sV[cur][(r + 8) * 68 + s * 8 + cq + 4];
            HMMA16(o1[0], o1[1], o1[2], o1[3],
                   pa[2 * s], pb[2 * s], pa[2 * s + 1], pb[2 * s + 1], b2, b3);
        }

        if (c + 1 < NCHUNK) {
            int nxt = cur ^ 1;
            ((uint2*)sK[nxt])[t] = kreg;
            *(uint4*)&sV[nxt][pl * 68 + qw * 4] = vreg;
        }
        __syncthreads();
    }

    float ss_lo = __shfl_sync(0xffffffffu, o1[0], lane & ~3);
    float ss_hi = __shfl_sync(0xffffffffu, o1[2], lane & ~3);
    float inv_lo = 1.f / fmaxf(ss_lo, 1e-30f);
    float inv_hi = 1.f / fmaxf(ss_hi, 1e-30f);

    int n = nh >> 3, h = nh & 7;
    float* dst = g_o + ((size_t)n * HCH + h * 8 + cq * 2) * L + q0 + r;
    dst[0]     = o0[0] * inv_lo;
    dst[8]     = o0[2] * inv_hi;
    dst[L]     = o0[1] * inv_lo;
    dst[L + 8] = o0[3] * inv_hi;
}

// ============================================================
extern "C" void kernel_launch(void* const* d_in, const int* in_sizes, int n_in,
                              void* d_out, int out_size)
{
    const float* x     = (const float*)d_in[0];
    const float* qkv_w = (const float*)d_in[1];
    const float* qkv_b = (const float*)d_in[2];
    const float* pos_w = (const float*)d_in[3];
    const float* pos_b = (const float*)d_in[4];
    const float* res_w = (const float*)d_in[5];
    const float* res_b = (const float*)d_in[6];
    float* out = (float*)d_out;

    float* qkv_ptr = nullptr;
    float* o_ptr   = nullptr;
    cudaGetSymbolAddress((void**)&qkv_ptr, g_qkv);
    cudaGetSymbolAddress((void**)&o_ptr, g_o);
    uint4 *qwf, *rwf, *pwf;
    uint2 *xf2, *of2, *pf2;
    cudaGetSymbolAddress((void**)&qwf, g_qwf);
    cudaGetSymbolAddress((void**)&rwf, g_rwf);
    cudaGetSymbolAddress((void**)&pwf, g_pwf);
    cudaGetSymbolAddress((void**)&xf2, g_xf2);
    cudaGetSymbolAddress((void**)&of2, g_of2);
    cudaGetSymbolAddress((void**)&pf2, g_pf2);

    // K0: zero g_qkv (atomicAdd target for K-split qkv GEMM)
    cudaMemsetAsync(qkv_ptr, 0, (size_t)NBATCH * 192 * L * sizeof(float));

    // K1a: build A-frags (qkv_w 192x512, res_w 512x64, pos_w 64x576)
    afrag_split_kernel<<<48, 256>>>(qkv_w, qwf, 512, 32, 12 * 32 * 32);
    afrag_split_kernel<<<16, 256>>>(res_w, rwf, 64, 4, 32 * 4 * 32);
    afrag_split_kernel<<<18, 256>>>(pos_w, pwf, 576, 36, 4 * 36 * 32);
    // K1b: build hi-only B-frags for x (smem-staged)
    bfrag_hi_staged_kernel<32><<<dim3(32, 9, NBATCH), 256>>>(x, xf2);
    // K1c: qkv GEMM (split-A x f16-B HMMA, K-split 2x, atomicAdd) -> g_qkv
    hgemm_bhi_kernel<32, 2, 1><<<dim3(36, 6, NBATCH), 256>>>(
        qwf, xf2, qkv_b, qkv_ptr, 192);

    // K2: attention fragment images
    {
        int total = NT_Q + NT_K + NT_V;
        convert_kernel<<<(total + 255) / 256, 256>>>();
    }

    // K3: attention (HMMA tensor cores) -> g_o
    attn_hmma_kernel<<<NNH * NQT, 256>>>();

    // K4a: build hi-only pos im2col B-frags from V
    {
        int total = NBATCH * NCB * 36 * 32;
        pfrag_hi_kernel<<<(total + 255) / 256, 256>>>(total);
    }
    // K4b: pos conv GEMM (split-A x f16-B, K-split 4x, atomicAdd into g_o)
    hgemm_bhi_kernel<36, 4, 1><<<dim3(36, 4, NBATCH), 256>>>(
        pwf, pf2, pos_b, o_ptr, 64);

    // K5a: build hi-only B-frags for attention+pos output (smem-staged)
    bfrag_hi_staged_kernel<4><<<dim3(4, 9, NBATCH), 256>>>(o_ptr, of2);
    // K5b: res GEMM (split-A x f16-B) -> out
    hgemm_bhi_kernel<4, 1, 0><<<dim3(36, 8, NBATCH), 256>>>(
        rwf, of2, res_b, out, 512);
}